// round 16
// baseline (speedup 1.0000x reference)
// SampleScoreModel: softmax-weighted Gaussian-kernel score (flash-attention style).
// Round 16 = round 15 resubmitted (broker container failure; kernel never ran).
// Dot GEMM re-tiled FAT-B — 128 active threads, thread = 8b x 8n
// (4 warps x 8 b-rows x 256 n). Halves st-tile LDS wavefronts in the dot loop
// (4608 -> 2560 wf/CTA), the measured binding resource. FMA2/DUP2 totals
// conserved. q stays fused (r14 win). K2 = r14 distributed reduce + PDL.
#include <cuda_runtime.h>
#include <math.h>
#include <float.h>

#define B 32
#define D 64
#define NS 65536
#define TILE 256
#define GRID_MAIN (NS / TILE)   // 256
#define THREADS 256

#define ST_STRIDE 256
#define G_STRIDE 256
#define XS_STRIDE 36

#define SW(n) ((n) ^ ((((n) >> 3) & 7) << 2))

// smem layout (floats)
#define OFF_ST 0                         // 64*256 = 16384
#define OFF_G  16384                     // 32*256 = 8192
#define OFF_XS 24576                     // 64*36  = 2304
#define OFF_CB 26880                     // 32
#define OFF_M  26912                     // 32
#define OFF_L  26944                     // 32
#define SMEM_FLOATS 26976
#define SMEM_BYTES (SMEM_FLOATS * 4)     // 107,904 B -> 2 CTAs/SM

#define FMA2(acc, a, b) \
    asm("fma.rn.f32x2 %0, %1, %2, %0;" : "+l"(acc) : "l"(a), "l"(b))
#define DUP2(d, f) \
    asm("mov.b64 %0, {%1, %1};" : "=l"(d) : "r"(__float_as_uint(f)))

__device__ __forceinline__ float lo32(unsigned long long u) {
    return __uint_as_float((unsigned)u);
}
__device__ __forceinline__ float hi32(unsigned long long u) {
    return __uint_as_float((unsigned)(u >> 32));
}

__device__ float g_acc[GRID_MAIN][B][D];
__device__ float g_mT[B][GRID_MAIN];
__device__ float g_lT[B][GRID_MAIN];

__global__ __launch_bounds__(THREADS, 2)
void score_partial_kernel(const float* __restrict__ t,
                          const float* __restrict__ x,
                          const float* __restrict__ samples) {
    extern __shared__ float sm[];
    float* st   = sm + OFF_ST;
    float* G    = sm + OFF_G;
    float* xs   = sm + OFF_XS;
    float* cb_s = sm + OFF_CB;
    float* m_s  = sm + OFF_M;
    float* l_s  = sm + OFF_L;

    const int tid = threadIdx.x;

    // ---- coalesced global load issued FIRST (16-deep MLP in flight) ----
    const int nn2 = tid >> 4;
    const int d4  = tid & 15;
    const float4* sp = (const float4*)samples;
    const size_t base = (size_t)blockIdx.x * (TILE * (D / 4));
    float4 v[16];
#pragma unroll
    for (int j = 0; j < 16; j++) v[j] = sp[base + tid + 256 * j];

    // ---- setup: x transpose + per-b constants (overlaps inflight loads) ----
#pragma unroll
    for (int i = tid; i < B * D; i += THREADS) {
        int b = i >> 6, k = i & 63;
        xs[k * XS_STRIDE + b] = x[i];
    }
    if (tid < B) {
        float sig = 0.01f * expf(t[tid] * 9.210340371976184f);
        cb_s[tid] = 0.5f / (sig * sig);
    }

    // ---- transpose-store into st with d-dependent swizzle ----
    const int h4st = (d4 >> 1) << 2;
#pragma unroll
    for (int j = 0; j < 16; j++) {
        int n = 16 * j + nn2;
        int pc = SW(n) ^ h4st;
        float* p = &st[(4 * d4) * ST_STRIDE + pc];
        p[0 * ST_STRIDE] = v[j].x;
        p[1 * ST_STRIDE] = v[j].y;
        p[2 * ST_STRIDE] = v[j].z;
        p[3 * ST_STRIDE] = v[j].w;
    }
    __syncthreads();

    // ---- dot GEMM, FAT-B: 4 active warps, thread = 8b x 8n; q fused ----
    const int w    = tid >> 5;
    const int lane = tid & 31;
    if (w < 4) {
        const int b0  = 8 * w;
        const int pnA = SW(8 * lane);

        unsigned long long dot2[8][4];
        unsigned long long q2[4];
#pragma unroll
        for (int a = 0; a < 8; a++)
#pragma unroll
            for (int jp = 0; jp < 4; jp++) dot2[a][jp] = 0ull;
#pragma unroll
        for (int jp = 0; jp < 4; jp++) q2[jp] = 0ull;

#pragma unroll 1
        for (int k0 = 0; k0 < D; k0 += 8) {
            const int hk = (k0 >> 3) << 2;
            const int pA = pnA ^ hk;
#pragma unroll
            for (int kk = 0; kk < 8; kk++) {
                const int k = k0 + kk;
                const float4 xv0 = *(const float4*)&xs[k * XS_STRIDE + b0];
                const float4 xv1 = *(const float4*)&xs[k * XS_STRIDE + b0 + 4];
                unsigned long long xd0, xd1, xd2, xd3, xd4, xd5, xd6, xd7;
                DUP2(xd0, xv0.x); DUP2(xd1, xv0.y); DUP2(xd2, xv0.z); DUP2(xd3, xv0.w);
                DUP2(xd4, xv1.x); DUP2(xd5, xv1.y); DUP2(xd6, xv1.z); DUP2(xd7, xv1.w);
                const ulonglong2 s01 = *(const ulonglong2*)&st[k * ST_STRIDE + pA];
                const ulonglong2 s23 = *(const ulonglong2*)&st[k * ST_STRIDE + (pA ^ 4)];
                FMA2(dot2[0][0], xd0, s01.x); FMA2(dot2[0][1], xd0, s01.y);
                FMA2(dot2[0][2], xd0, s23.x); FMA2(dot2[0][3], xd0, s23.y);
                FMA2(dot2[1][0], xd1, s01.x); FMA2(dot2[1][1], xd1, s01.y);
                FMA2(dot2[1][2], xd1, s23.x); FMA2(dot2[1][3], xd1, s23.y);
                FMA2(dot2[2][0], xd2, s01.x); FMA2(dot2[2][1], xd2, s01.y);
                FMA2(dot2[2][2], xd2, s23.x); FMA2(dot2[2][3], xd2, s23.y);
                FMA2(dot2[3][0], xd3, s01.x); FMA2(dot2[3][1], xd3, s01.y);
                FMA2(dot2[3][2], xd3, s23.x); FMA2(dot2[3][3], xd3, s23.y);
                FMA2(dot2[4][0], xd4, s01.x); FMA2(dot2[4][1], xd4, s01.y);
                FMA2(dot2[4][2], xd4, s23.x); FMA2(dot2[4][3], xd4, s23.y);
                FMA2(dot2[5][0], xd5, s01.x); FMA2(dot2[5][1], xd5, s01.y);
                FMA2(dot2[5][2], xd5, s23.x); FMA2(dot2[5][3], xd5, s23.y);
                FMA2(dot2[6][0], xd6, s01.x); FMA2(dot2[6][1], xd6, s01.y);
                FMA2(dot2[6][2], xd6, s23.x); FMA2(dot2[6][3], xd6, s23.y);
                FMA2(dot2[7][0], xd7, s01.x); FMA2(dot2[7][1], xd7, s01.y);
                FMA2(dot2[7][2], xd7, s23.x); FMA2(dot2[7][3], xd7, s23.y);
                FMA2(q2[0], s01.x, s01.x);    FMA2(q2[1], s01.y, s01.y);
                FMA2(q2[2], s23.x, s23.x);    FMA2(q2[3], s23.y, s23.y);
            }
        }

        const float qv[8] = {lo32(q2[0]), hi32(q2[0]), lo32(q2[1]), hi32(q2[1]),
                             lo32(q2[2]), hi32(q2[2]), lo32(q2[3]), hi32(q2[3])};

#pragma unroll
        for (int a = 0; a < 8; a++) {
            const float c = cb_s[b0 + a];
            float gv[8];
#pragma unroll
            for (int jp = 0; jp < 4; jp++) {
                gv[2 * jp    ] = c * (2.0f * lo32(dot2[a][jp]) - qv[2 * jp]);
                gv[2 * jp + 1] = c * (2.0f * hi32(dot2[a][jp]) - qv[2 * jp + 1]);
            }
            float m = gv[0];
#pragma unroll
            for (int i = 1; i < 8; i++) m = fmaxf(m, gv[i]);
#pragma unroll
            for (int s = 16; s; s >>= 1) m = fmaxf(m, __shfl_xor_sync(0xffffffffu, m, s));
            float l = 0.0f;
#pragma unroll
            for (int i = 0; i < 8; i++) {
                float p = __expf(gv[i] - m);
                gv[i] = p;
                l += p;
            }
            *(float4*)&G[(b0 + a) * G_STRIDE + pnA] =
                make_float4(gv[0], gv[1], gv[2], gv[3]);
            *(float4*)&G[(b0 + a) * G_STRIDE + (pnA ^ 4)] =
                make_float4(gv[4], gv[5], gv[6], gv[7]);
#pragma unroll
            for (int s = 16; s; s >>= 1) l += __shfl_xor_sync(0xffffffffu, l, s);
            if (lane == 0) { m_s[b0 + a] = m; l_s[b0 + a] = l; }
        }
    }
    __syncthreads();

    // ---- acc GEMM (f32x2): 4b x 8d/thread, n split 4-way ----
    const int qg   = tid >> 6;
    const int cell = tid & 63;
    const int dg   = cell & 7;
    const int bg2  = cell >> 3;
    const int b0a  = 4 * bg2;
    const int d0   = 8 * dg;
    const int hd   = dg << 2;

    unsigned long long acc2[4][8];
#pragma unroll
    for (int a = 0; a < 4; a++)
#pragma unroll
        for (int r = 0; r < 8; r++) acc2[a][r] = 0ull;

    {
        const int nbase = 64 * qg;
#pragma unroll 2
        for (int n4 = 0; n4 < 64; n4 += 4) {
            const int pg = SW(nbase + n4);
            const int ps = pg ^ hd;
            const ulonglong2 p0 = *(const ulonglong2*)&G[(b0a + 0) * G_STRIDE + pg];
            const ulonglong2 p1 = *(const ulonglong2*)&G[(b0a + 1) * G_STRIDE + pg];
            const ulonglong2 p2 = *(const ulonglong2*)&G[(b0a + 2) * G_STRIDE + pg];
            const ulonglong2 p3 = *(const ulonglong2*)&G[(b0a + 3) * G_STRIDE + pg];
#pragma unroll
            for (int r = 0; r < 8; r++) {
                const ulonglong2 sv = *(const ulonglong2*)&st[(d0 + r) * ST_STRIDE + ps];
                FMA2(acc2[0][r], p0.x, sv.x); FMA2(acc2[0][r], p0.y, sv.y);
                FMA2(acc2[1][r], p1.x, sv.x); FMA2(acc2[1][r], p1.y, sv.y);
                FMA2(acc2[2][r], p2.x, sv.x); FMA2(acc2[2][r], p2.y, sv.y);
                FMA2(acc2[3][r], p3.x, sv.x); FMA2(acc2[3][r], p3.y, sv.y);
            }
        }
    }

    float acc[4][8];
#pragma unroll
    for (int a = 0; a < 4; a++)
#pragma unroll
        for (int r = 0; r < 8; r++)
            acc[a][r] = lo32(acc2[a][r]) + hi32(acc2[a][r]);

    __syncthreads();            // done reading G; reuse as combine buffer

    float* buf = G;
    {
        float* bp = &buf[(qg * 64 + cell) * 32];
#pragma unroll
        for (int a = 0; a < 4; a++) {
            *(float4*)&bp[a * 8 + 0] = make_float4(acc[a][0], acc[a][1], acc[a][2], acc[a][3]);
            *(float4*)&bp[a * 8 + 4] = make_float4(acc[a][4], acc[a][5], acc[a][6], acc[a][7]);
        }
    }
    __syncthreads();
    {
        const int a2 = tid >> 6;
        const int c2 = tid & 63;
        float4 sA = make_float4(0.f, 0.f, 0.f, 0.f);
        float4 sB = make_float4(0.f, 0.f, 0.f, 0.f);
#pragma unroll
        for (int q2i = 0; q2i < 4; q2i++) {
            const float* bp = &buf[(q2i * 64 + c2) * 32 + a2 * 8];
            const float4 uA = *(const float4*)&bp[0];
            const float4 uB = *(const float4*)&bp[4];
            sA.x += uA.x; sA.y += uA.y; sA.z += uA.z; sA.w += uA.w;
            sB.x += uB.x; sB.y += uB.y; sB.z += uB.z; sB.w += uB.w;
        }
        const int bglob = 4 * (c2 >> 3) + a2;
        const int dbase = 8 * (c2 & 7);
        *(float4*)&g_acc[blockIdx.x][bglob][dbase + 0] = sA;
        *(float4*)&g_acc[blockIdx.x][bglob][dbase + 4] = sB;
    }
    if (tid < B) {
        g_mT[tid][blockIdx.x] = m_s[tid];
        g_lT[tid][blockIdx.x] = l_s[tid];
    }
}

// Distributed reduce: CTA owns (b = blk&31, d-octet = blk>>5); loads hoisted.
__global__ __launch_bounds__(256)
void score_reduce_kernel(const float* __restrict__ t,
                         const float* __restrict__ x,
                         float* __restrict__ out) {
    const int b   = blockIdx.x & 31;
    const int d0r = (blockIdx.x >> 5) * 8;
    const int tid = threadIdx.x;
    __shared__ float red[416];

    cudaGridDependencySynchronize();   // wait for score_partial_kernel

    const float mi = g_mT[b][tid];
    const float li = g_lT[b][tid];
    const float4 aA = *(const float4*)&g_acc[tid][b][d0r];
    const float4 aB = *(const float4*)&g_acc[tid][b][d0r + 4];

    red[tid] = mi;
    __syncthreads();
    if (tid < 32) {
        float m = red[tid];
#pragma unroll
        for (int k = 1; k < 8; k++) m = fmaxf(m, red[tid + 32 * k]);
#pragma unroll
        for (int s = 16; s; s >>= 1) m = fmaxf(m, __shfl_xor_sync(0xffffffffu, m, s));
        if (tid == 0) red[300] = m;
    }
    __syncthreads();
    const float M = red[300];

    const float ei = __expf(mi - M);
    float vals[9];
    vals[0] = ei * li;
    vals[1] = ei * aA.x; vals[2] = ei * aA.y; vals[3] = ei * aA.z; vals[4] = ei * aA.w;
    vals[5] = ei * aB.x; vals[6] = ei * aB.y; vals[7] = ei * aB.z; vals[8] = ei * aB.w;
#pragma unroll
    for (int s = 16; s; s >>= 1)
#pragma unroll
        for (int j = 0; j < 9; j++)
            vals[j] += __shfl_xor_sync(0xffffffffu, vals[j], s);
    const int w2 = tid >> 5;
    if ((tid & 31) == 0) {
#pragma unroll
        for (int j = 0; j < 9; j++) red[320 + w2 * 12 + j] = vals[j];
    }
    __syncthreads();
    if (tid < 8) {
        float L = 0.0f, A = 0.0f;
#pragma unroll
        for (int w3 = 0; w3 < 8; w3++) {
            L += red[320 + w3 * 12 + 0];
            A += red[320 + w3 * 12 + 1 + tid];
        }
        const float sig = 0.01f * expf(t[b] * 9.210340371976184f);
        out[b * D + d0r + tid] = (1.0f / sig) * (A / L - x[b * D + d0r + tid]);
    }
}

extern "C" void kernel_launch(void* const* d_in, const int* in_sizes, int n_in,
                              void* d_out, int out_size) {
    const float* t = nullptr;
    const float* x = nullptr;
    const float* s = nullptr;
    for (int i = 0; i < n_in; i++) {
        if      (in_sizes[i] == B)      t = (const float*)d_in[i];
        else if (in_sizes[i] == B * D)  x = (const float*)d_in[i];
        else if (in_sizes[i] == NS * D) s = (const float*)d_in[i];
    }
    cudaFuncSetAttribute(score_partial_kernel,
                         cudaFuncAttributeMaxDynamicSharedMemorySize, SMEM_BYTES);
    score_partial_kernel<<<GRID_MAIN, THREADS, SMEM_BYTES>>>(t, x, s);

    cudaLaunchAttribute attrs[1];
    attrs[0].id = cudaLaunchAttributeProgrammaticStreamSerialization;
    attrs[0].val.programmaticStreamSerializationAllowed = 1;
    cudaLaunchConfig_t cfg = {};
    cfg.gridDim = dim3(GRID_MAIN, 1, 1);
    cfg.blockDim = dim3(256, 1, 1);
    cfg.dynamicSmemBytes = 0;
    cfg.stream = 0;
    cfg.attrs = attrs;
    cfg.numAttrs = 1;
    cudaLaunchKernelEx(&cfg, score_reduce_kernel, t, x, (float*)d_out);
}